// round 2
// baseline (speedup 1.0000x reference)
#include <cuda_runtime.h>
#include <cuda_bf16.h>
#include <math.h>

// Problem constants (fixed by the dataset)
#define NN   20000     // nodes
#define NE   100000    // edges (without self loops)
#define NR   1000      // relations
#define NF   128       // feature dim
#define NH   4         // heads
#define NL   4         // layers
#define HC   512       // NH*NF
#define ETOT (NE + NN) // edges incl self loops = 120000

// ---------------- scratch (static device globals; no runtime allocation) ----
__device__ float g_XL[(size_t)NN * HC];        // 41 MB  source projection
__device__ float g_XR[(size_t)NN * HC];        // 41 MB  target projection
__device__ float g_REL[(size_t)(NR + 1) * HC]; // 2 MB   edge embeddings (row NR = mean)
__device__ float g_relext[(size_t)(NR + 1) * NF]; // relations + mean row
__device__ float g_H[2 * (size_t)NN * NF];     // ping-pong node features
__device__ float g_logits[(size_t)ETOT * NH];  // per-edge per-head logits
__device__ int   g_cnt[NN];
__device__ int   g_rcnt[NR];
__device__ int   g_rowptr[NN + 1];
__device__ int   g_offs[NN];
__device__ int   g_esrc[ETOT];
__device__ int   g_edst[ETOT];
__device__ int   g_erel[ETOT];

// ---------------- preprocessing kernels -------------------------------------
__global__ void k_reset() {
    int i = blockIdx.x * blockDim.x + threadIdx.x;
    if (i < NN) g_cnt[i] = 1;              // self loop pre-counted
    if (i < NR) g_rcnt[i] = 0;
}

__global__ void k_hist(const int* __restrict__ ei, const int* __restrict__ relidx) {
    int e = blockIdx.x * blockDim.x + threadIdx.x;
    if (e < NE) {
        atomicAdd(&g_cnt[ei[NE + e]], 1);  // dst row
        atomicAdd(&g_rcnt[relidx[e]], 1);
    }
}

// single-block scan over 20000 counts -> rowptr + offs
__global__ void k_scan() {
    __shared__ int s[1024];
    int t = threadIdx.x;
    const int CH = 20;                      // 1024*20 >= 20000
    int beg = t * CH, end = min(beg + CH, NN);
    int sum = 0;
    for (int i = beg; i < end; i++) sum += g_cnt[i];
    s[t] = sum;
    __syncthreads();
    for (int off = 1; off < 1024; off <<= 1) {
        int v = (t >= off) ? s[t - off] : 0;
        __syncthreads();
        s[t] += v;
        __syncthreads();
    }
    int base = (t == 0) ? 0 : s[t - 1];
    for (int i = beg; i < end; i++) {
        g_rowptr[i] = base;
        g_offs[i]   = base;
        base += g_cnt[i];
    }
    if (t == 1023) g_rowptr[NN] = s[1023];
}

// mean edge-attr row: ea_mean = sum_r cnt[r]*relations[r] / NE -> relext row NR
__global__ void k_eamean(const float* __restrict__ relations) {
    __shared__ int rc[NR];
    for (int i = threadIdx.x; i < NR; i += blockDim.x) rc[i] = g_rcnt[i];
    __syncthreads();
    int f = threadIdx.x;                    // 128 threads
    float s = 0.0f;
    for (int r = 0; r < NR; r++) s += (float)rc[r] * relations[r * NF + f];
    g_relext[(size_t)NR * NF + f] = s * (1.0f / NE);
}

__global__ void k_copyrel(const float* __restrict__ relations) {
    int i = blockIdx.x * blockDim.x + threadIdx.x;
    if (i < NR * NF) g_relext[i] = relations[i];
}

__global__ void k_scatter(const int* __restrict__ ei, const int* __restrict__ relidx) {
    int e = blockIdx.x * blockDim.x + threadIdx.x;
    if (e >= NE) return;
    int s = ei[e], d = ei[NE + e];
    int pos = atomicAdd(&g_offs[d], 1);
    g_esrc[pos] = s;
    g_edst[pos] = d;
    g_erel[pos] = relidx[e];
}

__global__ void k_selfloop() {
    int n = blockIdx.x * blockDim.x + threadIdx.x;
    if (n >= NN) return;
    int pos = atomicAdd(&g_offs[n], 1);
    g_esrc[pos] = n;
    g_edst[pos] = n;
    g_erel[pos] = NR;                       // mean-attr row
}

// ---------------- GEMM: C[M][512] = A[M][128] @ B[128][512] (+bias) ---------
__global__ void __launch_bounds__(256)
gemm_k128(const float* __restrict__ A, const float* __restrict__ B,
          const float* __restrict__ bias, float* __restrict__ C, int M) {
    __shared__ float As[64 * 128];          // 32 KB
    __shared__ float Bs[64 * 64];           // 16 KB
    int t = threadIdx.x;
    int m0 = blockIdx.y * 64, n0 = blockIdx.x * 64;

    // load A tile 64x128 (zero-pad tail rows)
#pragma unroll
    for (int i = 0; i < 8; i++) {
        int flat = i * 256 + t;
        int row = flat >> 5, k4 = flat & 31;
        float4 v = make_float4(0.f, 0.f, 0.f, 0.f);
        int gr = m0 + row;
        if (gr < M) v = __ldg((const float4*)A + (size_t)gr * 32 + k4);
        *(float4*)&As[row * 128 + k4 * 4] = v;
    }

    int tx = t & 15, ty = t >> 4;
    int tm = ty * 4, tn = tx * 4;
    float acc[4][4] = {};

    for (int kh = 0; kh < 2; kh++) {
        __syncthreads();
        // load B half: 64 k-rows x 64 cols
#pragma unroll
        for (int i = 0; i < 4; i++) {
            int flat = i * 256 + t;
            int kr = flat >> 4, n4 = flat & 15;
            float4 v = __ldg((const float4*)(B + (size_t)(kh * 64 + kr) * HC + n0) + n4);
            *(float4*)&Bs[kr * 64 + n4 * 4] = v;
        }
        __syncthreads();
#pragma unroll 4
        for (int k4 = 0; k4 < 16; k4++) {
            float4 b0 = *(float4*)&Bs[(k4 * 4 + 0) * 64 + tn];
            float4 b1 = *(float4*)&Bs[(k4 * 4 + 1) * 64 + tn];
            float4 b2 = *(float4*)&Bs[(k4 * 4 + 2) * 64 + tn];
            float4 b3 = *(float4*)&Bs[(k4 * 4 + 3) * 64 + tn];
#pragma unroll
            for (int i = 0; i < 4; i++) {
                float4 a = *(float4*)&As[(tm + i) * 128 + kh * 64 + k4 * 4];
                acc[i][0] += a.x * b0.x + a.y * b1.x + a.z * b2.x + a.w * b3.x;
                acc[i][1] += a.x * b0.y + a.y * b1.y + a.z * b2.y + a.w * b3.y;
                acc[i][2] += a.x * b0.z + a.y * b1.z + a.z * b2.z + a.w * b3.z;
                acc[i][3] += a.x * b0.w + a.y * b1.w + a.z * b2.w + a.w * b3.w;
            }
        }
    }

    float4 bi = make_float4(0.f, 0.f, 0.f, 0.f);
    if (bias) bi = __ldg((const float4*)(bias + n0) + tx);
#pragma unroll
    for (int i = 0; i < 4; i++) {
        int gr = m0 + tm + i;
        if (gr < M) {
            float4 o = make_float4(acc[i][0] + bi.x, acc[i][1] + bi.y,
                                   acc[i][2] + bi.z, acc[i][3] + bi.w);
            *((float4*)(C + (size_t)gr * HC + n0) + tx) = o;
        }
    }
}

// ---------------- edge scoring: one warp per edge ---------------------------
// logits[e][h] = sum_c att[h][c] * leaky_relu(XL[src][h*128+c] + XR[dst][h*128+c] + REL[rel][h*128+c])
__global__ void k_score(const float* __restrict__ att_l) {
    int gt = blockIdx.x * blockDim.x + threadIdx.x;
    int e = gt >> 5;
    int lane = gt & 31;
    if (e >= ETOT) return;
    int s = g_esrc[e], d = g_edst[e], r = g_erel[e];
    const float4* xl4 = (const float4*)g_XL + (size_t)s * 128;
    const float4* xr4 = (const float4*)g_XR + (size_t)d * 128;
    const float4* rr4 = (const float4*)g_REL + (size_t)r * 128;
    const float4* at4 = (const float4*)att_l;
    float acc[NH];
#pragma unroll
    for (int h = 0; h < NH; h++) {
        int o = h * 32 + lane;
        float4 a = __ldg(xl4 + o);
        float4 b = __ldg(xr4 + o);
        float4 c = __ldg(rr4 + o);
        float4 w = __ldg(at4 + o);
        float vx = a.x + b.x + c.x; vx = vx > 0.f ? vx : 0.2f * vx;
        float vy = a.y + b.y + c.y; vy = vy > 0.f ? vy : 0.2f * vy;
        float vz = a.z + b.z + c.z; vz = vz > 0.f ? vz : 0.2f * vz;
        float vw = a.w + b.w + c.w; vw = vw > 0.f ? vw : 0.2f * vw;
        acc[h] = vx * w.x + vy * w.y + vz * w.z + vw * w.w;
    }
#pragma unroll
    for (int off = 16; off; off >>= 1) {
        acc[0] += __shfl_xor_sync(0xFFFFFFFFu, acc[0], off);
        acc[1] += __shfl_xor_sync(0xFFFFFFFFu, acc[1], off);
        acc[2] += __shfl_xor_sync(0xFFFFFFFFu, acc[2], off);
        acc[3] += __shfl_xor_sync(0xFFFFFFFFu, acc[3], off);
    }
    if (lane == 0)
        ((float4*)g_logits)[e] = make_float4(acc[0], acc[1], acc[2], acc[3]);
}

// ---------------- segment softmax + aggregation: one warp per dst node ------
__global__ void k_agg(const float* __restrict__ bias_l, float* __restrict__ Hout) {
    int gt = blockIdx.x * blockDim.x + threadIdx.x;
    int n = gt >> 5;
    int lane = gt & 31;
    if (n >= NN) return;
    int b0 = g_rowptr[n], b1 = g_rowptr[n + 1];
    const float4* lg4 = (const float4*)g_logits;

    float4 m = make_float4(-1e30f, -1e30f, -1e30f, -1e30f);
    for (int i = b0; i < b1; i++) {
        float4 v = __ldg(lg4 + i);
        m.x = fmaxf(m.x, v.x); m.y = fmaxf(m.y, v.y);
        m.z = fmaxf(m.z, v.z); m.w = fmaxf(m.w, v.w);
    }
    float4 den = make_float4(0.f, 0.f, 0.f, 0.f);
    for (int i = b0; i < b1; i++) {
        float4 v = __ldg(lg4 + i);
        den.x += __expf(v.x - m.x); den.y += __expf(v.y - m.y);
        den.z += __expf(v.z - m.z); den.w += __expf(v.w - m.w);
    }
    float4 inv = make_float4(1.f / den.x, 1.f / den.y, 1.f / den.z, 1.f / den.w);

    const float4* XL4 = (const float4*)g_XL;
    float4 acc = make_float4(0.f, 0.f, 0.f, 0.f);
    for (int i = b0; i < b1; i++) {
        float4 v = __ldg(lg4 + i);
        float w0 = __expf(v.x - m.x) * inv.x;
        float w1 = __expf(v.y - m.y) * inv.y;
        float w2 = __expf(v.z - m.z) * inv.z;
        float w3 = __expf(v.w - m.w) * inv.w;
        size_t base = (size_t)g_esrc[i] * 128;
        float4 x0 = __ldg(XL4 + base + 0 * 32 + lane);
        float4 x1 = __ldg(XL4 + base + 1 * 32 + lane);
        float4 x2 = __ldg(XL4 + base + 2 * 32 + lane);
        float4 x3 = __ldg(XL4 + base + 3 * 32 + lane);
        acc.x += w0 * x0.x + w1 * x1.x + w2 * x2.x + w3 * x3.x;
        acc.y += w0 * x0.y + w1 * x1.y + w2 * x2.y + w3 * x3.y;
        acc.z += w0 * x0.z + w1 * x1.z + w2 * x2.z + w3 * x3.z;
        acc.w += w0 * x0.w + w1 * x1.w + w2 * x2.w + w3 * x3.w;
    }
    float4 bi = __ldg((const float4*)bias_l + lane);
    float4 o = make_float4(acc.x * 0.25f + bi.x, acc.y * 0.25f + bi.y,
                           acc.z * 0.25f + bi.z, acc.w * 0.25f + bi.w);
    ((float4*)Hout)[(size_t)n * 32 + lane] = o;
}

// ---------------- output assembly -------------------------------------------
__global__ void k_output(const float* __restrict__ H, const float* __restrict__ relations,
                         float* __restrict__ out, int out_size) {
    int i = blockIdx.x * blockDim.x + threadIdx.x;
    if (i < NN * NF) out[i] = H[i];
    if (i < NR * NF && out_size >= NN * NF + NR * NF)
        out[NN * NF + i] = relations[i];
}

// ---------------- launch ------------------------------------------------------
extern "C" void kernel_launch(void* const* d_in, const int* in_sizes, int n_in,
                              void* d_out, int out_size) {
    const float* x         = (const float*)d_in[0];
    const int*   ei        = (const int*)d_in[1];
    const float* relations = (const float*)d_in[2];
    const int*   relidx    = (const int*)d_in[3];
    const float* Wl        = (const float*)d_in[4];
    const float* bl        = (const float*)d_in[5];
    const float* Wr        = (const float*)d_in[6];
    const float* br        = (const float*)d_in[7];
    const float* We        = (const float*)d_in[8];
    const float* att       = (const float*)d_in[9];
    const float* bias      = (const float*)d_in[10];

    float *pXL, *pXR, *pREL, *pRelext, *pH;
    cudaGetSymbolAddress((void**)&pXL, g_XL);
    cudaGetSymbolAddress((void**)&pXR, g_XR);
    cudaGetSymbolAddress((void**)&pREL, g_REL);
    cudaGetSymbolAddress((void**)&pRelext, g_relext);
    cudaGetSymbolAddress((void**)&pH, g_H);

    // ---- preprocessing (rebuilt every call: graph replay safe) ----
    k_reset<<<(NN + 255) / 256, 256>>>();
    k_hist<<<(NE + 255) / 256, 256>>>(ei, relidx);
    k_scan<<<1, 1024>>>();
    k_eamean<<<1, 128>>>(relations);
    k_copyrel<<<(NR * NF + 255) / 256, 256>>>(relations);
    k_scatter<<<(NE + 255) / 256, 256>>>(ei, relidx);
    k_selfloop<<<(NN + 255) / 256, 256>>>();

    dim3 gemm_grid_n(8, (NN + 63) / 64);
    dim3 gemm_grid_r(8, (NR + 1 + 63) / 64);

    const float* Hin = x;
    for (int l = 0; l < NL; l++) {
        const float* Wl_l = Wl + (size_t)l * NF * HC;
        const float* Wr_l = Wr + (size_t)l * NF * HC;
        const float* We_l = We + (size_t)l * NF * HC;
        gemm_k128<<<gemm_grid_n, 256>>>(Hin, Wl_l, bl + (size_t)l * HC, pXL, NN);
        gemm_k128<<<gemm_grid_n, 256>>>(Hin, Wr_l, br + (size_t)l * HC, pXR, NN);
        gemm_k128<<<gemm_grid_r, 256>>>(pRelext, We_l, nullptr, pREL, NR + 1);

        k_score<<<(ETOT * 32 + 255) / 256, 256>>>(att + (size_t)l * NH * NF);

        float* Hout = pH + (size_t)(l & 1) * NN * NF;
        k_agg<<<(NN * 32 + 255) / 256, 256>>>(bias + (size_t)l * NF, Hout);
        Hin = Hout;
    }

    k_output<<<(NN * NF + 255) / 256, 256>>>(Hin, relations, (float*)d_out, out_size);
}

// round 3
// speedup vs baseline: 1.4898x; 1.4898x over previous
#include <cuda_runtime.h>
#include <cuda_bf16.h>
#include <math.h>

// Problem constants (fixed by the dataset)
#define NN   20000     // nodes
#define NE   100000    // edges (without self loops)
#define NR   1000      // relations
#define NF   128       // feature dim
#define NH   4         // heads
#define NL   4         // layers
#define HC   512       // NH*NF
#define ETOT (NE + NN) // edges incl self loops = 120000

// ---------------- scratch (static device globals; no runtime allocation) ----
__device__ float g_XL[(size_t)NN * HC];        // 41 MB  source projection
__device__ float g_XR[(size_t)NN * HC];        // 41 MB  target projection
__device__ float g_REL[(size_t)(NR + 1) * HC]; // 2 MB   edge embeddings (row NR = mean)
__device__ float g_relext[(size_t)(NR + 1) * NF]; // relations + mean row
__device__ float g_H[2 * (size_t)NN * NF];     // ping-pong node features
__device__ float g_logits[(size_t)ETOT * NH];  // per-edge per-head logits
__device__ int   g_cnt[NN];
__device__ int   g_rcnt[NR];
__device__ int   g_rowptr[NN + 1];
__device__ int   g_offs[NN];
__device__ int   g_esrc[ETOT];
__device__ int   g_edst[ETOT];
__device__ int   g_erel[ETOT];

// ---------------- preprocessing kernels -------------------------------------
__global__ void k_reset() {
    int i = blockIdx.x * blockDim.x + threadIdx.x;
    if (i < NN) g_cnt[i] = 1;              // self loop pre-counted
    if (i < NR) g_rcnt[i] = 0;
}

__global__ void k_hist(const int* __restrict__ ei, const int* __restrict__ relidx) {
    int e = blockIdx.x * blockDim.x + threadIdx.x;
    if (e < NE) {
        atomicAdd(&g_cnt[ei[NE + e]], 1);  // dst row
        atomicAdd(&g_rcnt[relidx[e]], 1);
    }
}

// single-block scan over 20000 counts -> rowptr + offs
__global__ void k_scan() {
    __shared__ int s[1024];
    int t = threadIdx.x;
    const int CH = 20;                      // 1024*20 >= 20000
    int beg = t * CH, end = min(beg + CH, NN);
    int sum = 0;
    for (int i = beg; i < end; i++) sum += g_cnt[i];
    s[t] = sum;
    __syncthreads();
    for (int off = 1; off < 1024; off <<= 1) {
        int v = (t >= off) ? s[t - off] : 0;
        __syncthreads();
        s[t] += v;
        __syncthreads();
    }
    int base = (t == 0) ? 0 : s[t - 1];
    for (int i = beg; i < end; i++) {
        g_rowptr[i] = base;
        g_offs[i]   = base;
        base += g_cnt[i];
    }
    if (t == 1023) g_rowptr[NN] = s[1023];
}

// mean edge-attr row: ea_mean = sum_r cnt[r]*relations[r] / NE -> relext row NR
// 1024 threads: 8 relation-groups x 128 features, smem combine (deterministic)
__global__ void k_eamean(const float* __restrict__ relations) {
    __shared__ float part[8][NF];
    int t = threadIdx.x;
    int grp = t >> 7, f = t & 127;
    float s = 0.0f;
    for (int r = grp; r < NR; r += 8)
        s += (float)g_rcnt[r] * __ldg(relations + (size_t)r * NF + f);
    part[grp][f] = s;
    __syncthreads();
    if (grp == 0) {
        float tot = 0.0f;
#pragma unroll
        for (int i = 0; i < 8; i++) tot += part[i][f];
        g_relext[(size_t)NR * NF + f] = tot * (1.0f / NE);
    }
}

__global__ void k_copyrel(const float* __restrict__ relations) {
    int i = blockIdx.x * blockDim.x + threadIdx.x;
    if (i < NR * NF) g_relext[i] = relations[i];
}

__global__ void k_scatter(const int* __restrict__ ei, const int* __restrict__ relidx) {
    int e = blockIdx.x * blockDim.x + threadIdx.x;
    if (e >= NE) return;
    int s = ei[e], d = ei[NE + e];
    int pos = atomicAdd(&g_offs[d], 1);
    g_esrc[pos] = s;
    g_edst[pos] = d;
    g_erel[pos] = relidx[e];
}

__global__ void k_selfloop() {
    int n = blockIdx.x * blockDim.x + threadIdx.x;
    if (n >= NN) return;
    int pos = atomicAdd(&g_offs[n], 1);
    g_esrc[pos] = n;
    g_edst[pos] = n;
    g_erel[pos] = NR;                       // mean-attr row
}

// ---------------- tf32 tensor-core GEMM -------------------------------------
// C[M][512] = A[M][128] @ B[128][512] (+bias)
// CTA tile 128x128, K chunks of 32, mma.sync.m16n8k8.tf32 (HMMA path on sm_103a)
__device__ __forceinline__ unsigned f2tf(float x) {
    unsigned r;
    asm("cvt.rna.tf32.f32 %0, %1;" : "=r"(r) : "f"(x));
    return r;
}

__device__ __forceinline__ void mma_tf32(float* c, const unsigned* a,
                                         unsigned b0, unsigned b1) {
    asm("mma.sync.aligned.m16n8k8.row.col.f32.tf32.tf32.f32 "
        "{%0,%1,%2,%3},{%4,%5,%6,%7},{%8,%9},{%0,%1,%2,%3};"
        : "+f"(c[0]), "+f"(c[1]), "+f"(c[2]), "+f"(c[3])
        : "r"(a[0]), "r"(a[1]), "r"(a[2]), "r"(a[3]), "r"(b0), "r"(b1));
}

#define AS_STRIDE 36   // 4g+tg banks distinct mod 32, 144B rows (16B aligned)
#define BS_STRIDE 136  // 8tg+g banks distinct mod 32, 544B rows (16B aligned)

__global__ void __launch_bounds__(256)
gemm_tf32(const float* __restrict__ A, const float* __restrict__ B,
          const float* __restrict__ bias, float* __restrict__ C, int M) {
    __shared__ float As[128 * AS_STRIDE];   // 18.4 KB
    __shared__ float Bs[32 * BS_STRIDE];    // 17.4 KB
    int t = threadIdx.x;
    int warp = t >> 5, lane = t & 31;
    int g = lane >> 2, tg = lane & 3;
    int m0 = blockIdx.y * 128, n0 = blockIdx.x * 128;
    int wm = (warp >> 1) * 32;   // 4 warps along M
    int wn = (warp & 1) * 64;    // 2 warps along N

    float acc[2][8][4] = {};

    for (int kc = 0; kc < 4; kc++) {
        // A chunk: 128 rows x 32 cols (kc*32 ..)
#pragma unroll
        for (int i = 0; i < 4; i++) {
            int flat = i * 256 + t;
            int row = flat >> 3, c4 = flat & 7;
            float4 v = make_float4(0.f, 0.f, 0.f, 0.f);
            int gr = m0 + row;
            if (gr < M) v = __ldg((const float4*)(A + (size_t)gr * NF + kc * 32) + c4);
            *(float4*)&As[row * AS_STRIDE + c4 * 4] = v;
        }
        // B chunk: 32 k-rows x 128 cols
#pragma unroll
        for (int i = 0; i < 4; i++) {
            int flat = i * 256 + t;
            int kr = flat >> 5, c4 = flat & 31;
            float4 v = __ldg((const float4*)(B + (size_t)(kc * 32 + kr) * HC + n0) + c4);
            *(float4*)&Bs[kr * BS_STRIDE + c4 * 4] = v;
        }
        __syncthreads();

#pragma unroll
        for (int ks = 0; ks < 4; ks++) {
            int k0 = ks * 8;
            unsigned a[2][4];
#pragma unroll
            for (int mf = 0; mf < 2; mf++) {
                int r = wm + mf * 16 + g;
                a[mf][0] = f2tf(As[r * AS_STRIDE + k0 + tg]);
                a[mf][1] = f2tf(As[(r + 8) * AS_STRIDE + k0 + tg]);
                a[mf][2] = f2tf(As[r * AS_STRIDE + k0 + tg + 4]);
                a[mf][3] = f2tf(As[(r + 8) * AS_STRIDE + k0 + tg + 4]);
            }
#pragma unroll
            for (int nf = 0; nf < 8; nf++) {
                int c = wn + nf * 8 + g;
                unsigned b0 = f2tf(Bs[(k0 + tg) * BS_STRIDE + c]);
                unsigned b1 = f2tf(Bs[(k0 + tg + 4) * BS_STRIDE + c]);
                mma_tf32(acc[0][nf], a[0], b0, b1);
                mma_tf32(acc[1][nf], a[1], b0, b1);
            }
        }
        __syncthreads();
    }

    // epilogue: c0,c1 at (row, col..col+1); c2,c3 at (row+8, col..col+1)
#pragma unroll
    for (int nf = 0; nf < 8; nf++) {
        int col = n0 + wn + nf * 8 + 2 * tg;
        float2 bi = make_float2(0.f, 0.f);
        if (bias) bi = *(const float2*)(bias + col);
#pragma unroll
        for (int mf = 0; mf < 2; mf++) {
            int row = m0 + wm + mf * 16 + g;
            if (row < M) {
                float2 o = make_float2(acc[mf][nf][0] + bi.x, acc[mf][nf][1] + bi.y);
                *(float2*)(C + (size_t)row * HC + col) = o;
            }
            if (row + 8 < M) {
                float2 o = make_float2(acc[mf][nf][2] + bi.x, acc[mf][nf][3] + bi.y);
                *(float2*)(C + (size_t)(row + 8) * HC + col) = o;
            }
        }
    }
}

// ---------------- edge scoring: one warp per edge ---------------------------
__global__ void k_score(const float* __restrict__ att_l) {
    int gt = blockIdx.x * blockDim.x + threadIdx.x;
    int e = gt >> 5;
    int lane = gt & 31;
    if (e >= ETOT) return;
    int s = g_esrc[e], d = g_edst[e], r = g_erel[e];
    const float4* xl4 = (const float4*)g_XL + (size_t)s * 128;
    const float4* xr4 = (const float4*)g_XR + (size_t)d * 128;
    const float4* rr4 = (const float4*)g_REL + (size_t)r * 128;
    const float4* at4 = (const float4*)att_l;
    float acc[NH];
#pragma unroll
    for (int h = 0; h < NH; h++) {
        int o = h * 32 + lane;
        float4 a = __ldg(xl4 + o);
        float4 b = __ldg(xr4 + o);
        float4 c = __ldg(rr4 + o);
        float4 w = __ldg(at4 + o);
        float vx = a.x + b.x + c.x; vx = vx > 0.f ? vx : 0.2f * vx;
        float vy = a.y + b.y + c.y; vy = vy > 0.f ? vy : 0.2f * vy;
        float vz = a.z + b.z + c.z; vz = vz > 0.f ? vz : 0.2f * vz;
        float vw = a.w + b.w + c.w; vw = vw > 0.f ? vw : 0.2f * vw;
        acc[h] = vx * w.x + vy * w.y + vz * w.z + vw * w.w;
    }
#pragma unroll
    for (int off = 16; off; off >>= 1) {
        acc[0] += __shfl_xor_sync(0xFFFFFFFFu, acc[0], off);
        acc[1] += __shfl_xor_sync(0xFFFFFFFFu, acc[1], off);
        acc[2] += __shfl_xor_sync(0xFFFFFFFFu, acc[2], off);
        acc[3] += __shfl_xor_sync(0xFFFFFFFFu, acc[3], off);
    }
    if (lane == 0)
        ((float4*)g_logits)[e] = make_float4(acc[0], acc[1], acc[2], acc[3]);
}

// ---------------- segment softmax + aggregation: one warp per dst node ------
__global__ void k_agg(const float* __restrict__ bias_l, float* __restrict__ Hout) {
    int gt = blockIdx.x * blockDim.x + threadIdx.x;
    int n = gt >> 5;
    int lane = gt & 31;
    if (n >= NN) return;
    int b0 = g_rowptr[n], b1 = g_rowptr[n + 1];
    const float4* lg4 = (const float4*)g_logits;

    float4 m = make_float4(-1e30f, -1e30f, -1e30f, -1e30f);
    for (int i = b0; i < b1; i++) {
        float4 v = __ldg(lg4 + i);
        m.x = fmaxf(m.x, v.x); m.y = fmaxf(m.y, v.y);
        m.z = fmaxf(m.z, v.z); m.w = fmaxf(m.w, v.w);
    }
    float4 den = make_float4(0.f, 0.f, 0.f, 0.f);
    for (int i = b0; i < b1; i++) {
        float4 v = __ldg(lg4 + i);
        den.x += __expf(v.x - m.x); den.y += __expf(v.y - m.y);
        den.z += __expf(v.z - m.z); den.w += __expf(v.w - m.w);
    }
    float4 inv = make_float4(1.f / den.x, 1.f / den.y, 1.f / den.z, 1.f / den.w);

    const float4* XL4 = (const float4*)g_XL;
    float4 acc = make_float4(0.f, 0.f, 0.f, 0.f);
    for (int i = b0; i < b1; i++) {
        float4 v = __ldg(lg4 + i);
        float w0 = __expf(v.x - m.x) * inv.x;
        float w1 = __expf(v.y - m.y) * inv.y;
        float w2 = __expf(v.z - m.z) * inv.z;
        float w3 = __expf(v.w - m.w) * inv.w;
        size_t base = (size_t)g_esrc[i] * 128;
        float4 x0 = __ldg(XL4 + base + 0 * 32 + lane);
        float4 x1 = __ldg(XL4 + base + 1 * 32 + lane);
        float4 x2 = __ldg(XL4 + base + 2 * 32 + lane);
        float4 x3 = __ldg(XL4 + base + 3 * 32 + lane);
        acc.x += w0 * x0.x + w1 * x1.x + w2 * x2.x + w3 * x3.x;
        acc.y += w0 * x0.y + w1 * x1.y + w2 * x2.y + w3 * x3.y;
        acc.z += w0 * x0.z + w1 * x1.z + w2 * x2.z + w3 * x3.z;
        acc.w += w0 * x0.w + w1 * x1.w + w2 * x2.w + w3 * x3.w;
    }
    float4 bi = __ldg((const float4*)bias_l + lane);
    float4 o = make_float4(acc.x * 0.25f + bi.x, acc.y * 0.25f + bi.y,
                           acc.z * 0.25f + bi.z, acc.w * 0.25f + bi.w);
    ((float4*)Hout)[(size_t)n * 32 + lane] = o;
}

// ---------------- output assembly -------------------------------------------
__global__ void k_output(const float* __restrict__ H, const float* __restrict__ relations,
                         float* __restrict__ out, int out_size) {
    int i = blockIdx.x * blockDim.x + threadIdx.x;
    if (i < NN * NF) out[i] = H[i];
    if (i < NR * NF && out_size >= NN * NF + NR * NF)
        out[NN * NF + i] = relations[i];
}

// ---------------- launch ------------------------------------------------------
extern "C" void kernel_launch(void* const* d_in, const int* in_sizes, int n_in,
                              void* d_out, int out_size) {
    const float* x         = (const float*)d_in[0];
    const int*   ei        = (const int*)d_in[1];
    const float* relations = (const float*)d_in[2];
    const int*   relidx    = (const int*)d_in[3];
    const float* Wl        = (const float*)d_in[4];
    const float* bl        = (const float*)d_in[5];
    const float* Wr        = (const float*)d_in[6];
    const float* br        = (const float*)d_in[7];
    const float* We        = (const float*)d_in[8];
    const float* att       = (const float*)d_in[9];
    const float* bias      = (const float*)d_in[10];

    float *pXL, *pXR, *pREL, *pRelext, *pH;
    cudaGetSymbolAddress((void**)&pXL, g_XL);
    cudaGetSymbolAddress((void**)&pXR, g_XR);
    cudaGetSymbolAddress((void**)&pREL, g_REL);
    cudaGetSymbolAddress((void**)&pRelext, g_relext);
    cudaGetSymbolAddress((void**)&pH, g_H);

    // ---- preprocessing (rebuilt every call: graph replay safe) ----
    k_reset<<<(NN + 255) / 256, 256>>>();
    k_hist<<<(NE + 255) / 256, 256>>>(ei, relidx);
    k_scan<<<1, 1024>>>();
    k_eamean<<<1, 1024>>>(relations);
    k_copyrel<<<(NR * NF + 255) / 256, 256>>>(relations);
    k_scatter<<<(NE + 255) / 256, 256>>>(ei, relidx);
    k_selfloop<<<(NN + 255) / 256, 256>>>();

    dim3 grid_n(4, (NN + 127) / 128);       // 4 x 157
    dim3 grid_r(4, (NR + 1 + 127) / 128);   // 4 x 8

    const float* Hin = x;
    for (int l = 0; l < NL; l++) {
        const float* Wl_l = Wl + (size_t)l * NF * HC;
        const float* Wr_l = Wr + (size_t)l * NF * HC;
        const float* We_l = We + (size_t)l * NF * HC;
        gemm_tf32<<<grid_n, 256>>>(Hin, Wl_l, bl + (size_t)l * HC, pXL, NN);
        gemm_tf32<<<grid_n, 256>>>(Hin, Wr_l, br + (size_t)l * HC, pXR, NN);
        gemm_tf32<<<grid_r, 256>>>(pRelext, We_l, nullptr, pREL, NR + 1);

        k_score<<<(ETOT * 32 + 255) / 256, 256>>>(att + (size_t)l * NH * NF);

        float* Hout = pH + (size_t)(l & 1) * NN * NF;
        k_agg<<<(NN * 32 + 255) / 256, 256>>>(bias + (size_t)l * NF, Hout);
        Hin = Hout;
    }

    k_output<<<(NN * NF + 255) / 256, 256>>>(Hin, relations, (float*)d_out, out_size);
}

// round 4
// speedup vs baseline: 1.8137x; 1.2174x over previous
#include <cuda_runtime.h>
#include <cuda_bf16.h>
#include <math.h>

// Problem constants (fixed by the dataset)
#define NN   20000     // nodes
#define NE   100000    // edges (without self loops)
#define NR   1000      // relations
#define NF   128       // feature dim
#define NH   4         // heads
#define NL   4         // layers
#define HC   512       // NH*NF
#define ETOT (NE + NN) // edges incl self loops = 120000

// ---------------- scratch (static device globals; no runtime allocation) ----
__device__ float g_XL[(size_t)NN * HC];        // 41 MB  source projection
__device__ float g_XR[(size_t)NN * HC];        // 41 MB  target projection
__device__ float g_REL[(size_t)(NR + 1) * HC]; // 2 MB   edge embeddings (row NR = mean)
__device__ float g_relext[(size_t)(NR + 1) * NF]; // relations + mean row
__device__ float g_H[2 * (size_t)NN * NF];     // ping-pong node features
__device__ float g_part[64][NF];               // eamean partials
__device__ int   g_cnt[NN];
__device__ int   g_rcnt[NR];
__device__ int   g_rowptr[NN + 1];
__device__ int   g_offs[NN];
__device__ int   g_esrc[ETOT];
__device__ int   g_erel[ETOT];

// ---------------- preprocessing kernels -------------------------------------
__global__ void k_reset() {
    int i = blockIdx.x * blockDim.x + threadIdx.x;
    if (i < NN) g_cnt[i] = 1;              // self loop pre-counted
    if (i < NR) g_rcnt[i] = 0;
}

__global__ void k_hist(const int* __restrict__ ei, const int* __restrict__ relidx) {
    int e = blockIdx.x * blockDim.x + threadIdx.x;
    if (e < NE) {
        atomicAdd(&g_cnt[ei[NE + e]], 1);  // dst row
        atomicAdd(&g_rcnt[relidx[e]], 1);
    }
}

// single-block scan over 20000 counts -> rowptr + offs
__global__ void k_scan() {
    __shared__ int s[1024];
    int t = threadIdx.x;
    const int CH = 20;                      // 1024*20 >= 20000
    int beg = t * CH, end = min(beg + CH, NN);
    int sum = 0;
    for (int i = beg; i < end; i++) sum += g_cnt[i];
    s[t] = sum;
    __syncthreads();
    for (int off = 1; off < 1024; off <<= 1) {
        int v = (t >= off) ? s[t - off] : 0;
        __syncthreads();
        s[t] += v;
        __syncthreads();
    }
    int base = (t == 0) ? 0 : s[t - 1];
    for (int i = beg; i < end; i++) {
        g_rowptr[i] = base;
        g_offs[i]   = base;
        base += g_cnt[i];
    }
    if (t == 1023) g_rowptr[NN] = s[1023];
}

// eamean stage 1: 64 blocks x 128 threads, strided partial sums
__global__ void k_eamean1(const float* __restrict__ relations) {
    int b = blockIdx.x, f = threadIdx.x;
    float s = 0.0f;
    for (int r = b; r < NR; r += 64)
        s += (float)g_rcnt[r] * __ldg(relations + (size_t)r * NF + f);
    g_part[b][f] = s;
}

// eamean stage 2: combine 64 partials (deterministic)
__global__ void k_eamean2() {
    int f = threadIdx.x;
    float s = 0.0f;
#pragma unroll
    for (int b = 0; b < 64; b++) s += g_part[b][f];
    g_relext[(size_t)NR * NF + f] = s * (1.0f / NE);
}

__global__ void k_copyrel(const float* __restrict__ relations) {
    int i = blockIdx.x * blockDim.x + threadIdx.x;
    if (i < NR * NF) g_relext[i] = relations[i];
}

__global__ void k_scatter(const int* __restrict__ ei, const int* __restrict__ relidx) {
    int e = blockIdx.x * blockDim.x + threadIdx.x;
    if (e >= NE) return;
    int s = ei[e], d = ei[NE + e];
    int pos = atomicAdd(&g_offs[d], 1);
    g_esrc[pos] = s;
    g_erel[pos] = relidx[e];
}

__global__ void k_selfloop() {
    int n = blockIdx.x * blockDim.x + threadIdx.x;
    if (n >= NN) return;
    int pos = atomicAdd(&g_offs[n], 1);
    g_esrc[pos] = n;
    g_erel[pos] = NR;                       // mean-attr row
}

// ---------------- tf32 tensor-core GEMM -------------------------------------
// C[M][512] = A[M][128] @ B[128][512] (+bias)
__device__ __forceinline__ unsigned f2tf(float x) {
    unsigned r;
    asm("cvt.rna.tf32.f32 %0, %1;" : "=r"(r) : "f"(x));
    return r;
}

__device__ __forceinline__ void mma_tf32(float* c, const unsigned* a,
                                         unsigned b0, unsigned b1) {
    asm("mma.sync.aligned.m16n8k8.row.col.f32.tf32.tf32.f32 "
        "{%0,%1,%2,%3},{%4,%5,%6,%7},{%8,%9},{%0,%1,%2,%3};"
        : "+f"(c[0]), "+f"(c[1]), "+f"(c[2]), "+f"(c[3])
        : "r"(a[0]), "r"(a[1]), "r"(a[2]), "r"(a[3]), "r"(b0), "r"(b1));
}

#define AS_STRIDE 36
#define BS_STRIDE 136

__global__ void __launch_bounds__(256)
gemm_tf32(const float* __restrict__ A, const float* __restrict__ B,
          const float* __restrict__ bias, float* __restrict__ C, int M) {
    __shared__ float As[128 * AS_STRIDE];
    __shared__ float Bs[32 * BS_STRIDE];
    int t = threadIdx.x;
    int warp = t >> 5, lane = t & 31;
    int g = lane >> 2, tg = lane & 3;
    int m0 = blockIdx.y * 128, n0 = blockIdx.x * 128;
    int wm = (warp >> 1) * 32;
    int wn = (warp & 1) * 64;

    float acc[2][8][4] = {};

    for (int kc = 0; kc < 4; kc++) {
#pragma unroll
        for (int i = 0; i < 4; i++) {
            int flat = i * 256 + t;
            int row = flat >> 3, c4 = flat & 7;
            float4 v = make_float4(0.f, 0.f, 0.f, 0.f);
            int gr = m0 + row;
            if (gr < M) v = __ldg((const float4*)(A + (size_t)gr * NF + kc * 32) + c4);
            *(float4*)&As[row * AS_STRIDE + c4 * 4] = v;
        }
#pragma unroll
        for (int i = 0; i < 4; i++) {
            int flat = i * 256 + t;
            int kr = flat >> 5, c4 = flat & 31;
            float4 v = __ldg((const float4*)(B + (size_t)(kc * 32 + kr) * HC + n0) + c4);
            *(float4*)&Bs[kr * BS_STRIDE + c4 * 4] = v;
        }
        __syncthreads();

#pragma unroll
        for (int ks = 0; ks < 4; ks++) {
            int k0 = ks * 8;
            unsigned a[2][4];
#pragma unroll
            for (int mf = 0; mf < 2; mf++) {
                int r = wm + mf * 16 + g;
                a[mf][0] = f2tf(As[r * AS_STRIDE + k0 + tg]);
                a[mf][1] = f2tf(As[(r + 8) * AS_STRIDE + k0 + tg]);
                a[mf][2] = f2tf(As[r * AS_STRIDE + k0 + tg + 4]);
                a[mf][3] = f2tf(As[(r + 8) * AS_STRIDE + k0 + tg + 4]);
            }
#pragma unroll
            for (int nf = 0; nf < 8; nf++) {
                int c = wn + nf * 8 + g;
                unsigned b0 = f2tf(Bs[(k0 + tg) * BS_STRIDE + c]);
                unsigned b1 = f2tf(Bs[(k0 + tg + 4) * BS_STRIDE + c]);
                mma_tf32(acc[0][nf], a[0], b0, b1);
                mma_tf32(acc[1][nf], a[1], b0, b1);
            }
        }
        __syncthreads();
    }

#pragma unroll
    for (int nf = 0; nf < 8; nf++) {
        int col = n0 + wn + nf * 8 + 2 * tg;
        float2 bi = make_float2(0.f, 0.f);
        if (bias) bi = *(const float2*)(bias + col);
#pragma unroll
        for (int mf = 0; mf < 2; mf++) {
            int row = m0 + wm + mf * 16 + g;
            if (row < M) {
                float2 o = make_float2(acc[mf][nf][0] + bi.x, acc[mf][nf][1] + bi.y);
                *(float2*)(C + (size_t)row * HC + col) = o;
            }
            if (row + 8 < M) {
                float2 o = make_float2(acc[mf][nf][2] + bi.x, acc[mf][nf][3] + bi.y);
                *(float2*)(C + (size_t)(row + 8) * HC + col) = o;
            }
        }
    }
}

// ---------------- fused score + softmax + aggregate --------------------------
// One block (128 threads = 4 warps) per dst node; warp h owns head h.
// Online softmax: each XL[src] row read once; XR[dst] read once per node.
__global__ void __launch_bounds__(128)
k_fused(const float* __restrict__ att_l, const float* __restrict__ bias_l,
        float* __restrict__ Hout) {
    int n = blockIdx.x;
    int t = threadIdx.x;
    int h = t >> 5, lane = t & 31;
    int b0 = g_rowptr[n], b1 = g_rowptr[n + 1];

    int o = h * 32 + lane;                    // float4 index into a 512-f row
    const float4* XL4 = (const float4*)g_XL;
    const float4* RR4 = (const float4*)g_REL;
    float4 xr = __ldg((const float4*)g_XR + (size_t)n * 128 + o);
    float4 aw = __ldg((const float4*)att_l + o);

    float m = -1e30f, den = 0.0f;
    float4 acc = make_float4(0.f, 0.f, 0.f, 0.f);

    for (int i = b0; i < b1; i++) {
        int s = g_esrc[i], r = g_erel[i];
        float4 xl = __ldg(XL4 + (size_t)s * 128 + o);
        float4 rr = __ldg(RR4 + (size_t)r * 128 + o);
        float vx = xl.x + xr.x + rr.x; vx = vx > 0.f ? vx : 0.2f * vx;
        float vy = xl.y + xr.y + rr.y; vy = vy > 0.f ? vy : 0.2f * vy;
        float vz = xl.z + xr.z + rr.z; vz = vz > 0.f ? vz : 0.2f * vz;
        float vw = xl.w + xr.w + rr.w; vw = vw > 0.f ? vw : 0.2f * vw;
        float l = vx * aw.x + vy * aw.y + vz * aw.z + vw * aw.w;
#pragma unroll
        for (int off = 16; off; off >>= 1)
            l += __shfl_xor_sync(0xFFFFFFFFu, l, off);

        if (l > m) {                          // uniform across warp
            float sc = __expf(m - l);
            den *= sc;
            acc.x *= sc; acc.y *= sc; acc.z *= sc; acc.w *= sc;
            m = l;
        }
        float w = __expf(l - m);
        den += w;
        acc.x += w * xl.x; acc.y += w * xl.y;
        acc.z += w * xl.z; acc.w += w * xl.w;
    }

    // head mean (0.25/den) + cross-head combine via smem
    __shared__ float sacc[NH][NF];
    float sc = 0.25f / den;
    sacc[h][lane * 4 + 0] = acc.x * sc;
    sacc[h][lane * 4 + 1] = acc.y * sc;
    sacc[h][lane * 4 + 2] = acc.z * sc;
    sacc[h][lane * 4 + 3] = acc.w * sc;
    __syncthreads();
    float out = sacc[0][t] + sacc[1][t] + sacc[2][t] + sacc[3][t]
              + __ldg(bias_l + t);
    Hout[(size_t)n * NF + t] = out;
}

// ---------------- output assembly -------------------------------------------
__global__ void k_output(const float* __restrict__ H, const float* __restrict__ relations,
                         float* __restrict__ out, int out_size) {
    int i = blockIdx.x * blockDim.x + threadIdx.x;
    if (i < NN * NF) out[i] = H[i];
    if (i < NR * NF && out_size >= NN * NF + NR * NF)
        out[NN * NF + i] = relations[i];
}

// ---------------- launch ------------------------------------------------------
extern "C" void kernel_launch(void* const* d_in, const int* in_sizes, int n_in,
                              void* d_out, int out_size) {
    const float* x         = (const float*)d_in[0];
    const int*   ei        = (const int*)d_in[1];
    const float* relations = (const float*)d_in[2];
    const int*   relidx    = (const int*)d_in[3];
    const float* Wl        = (const float*)d_in[4];
    const float* bl        = (const float*)d_in[5];
    const float* Wr        = (const float*)d_in[6];
    const float* br        = (const float*)d_in[7];
    const float* We        = (const float*)d_in[8];
    const float* att       = (const float*)d_in[9];
    const float* bias      = (const float*)d_in[10];

    float *pXL, *pXR, *pREL, *pRelext, *pH;
    cudaGetSymbolAddress((void**)&pXL, g_XL);
    cudaGetSymbolAddress((void**)&pXR, g_XR);
    cudaGetSymbolAddress((void**)&pREL, g_REL);
    cudaGetSymbolAddress((void**)&pRelext, g_relext);
    cudaGetSymbolAddress((void**)&pH, g_H);

    // ---- preprocessing (rebuilt every call: graph replay safe) ----
    k_reset<<<(NN + 255) / 256, 256>>>();
    k_hist<<<(NE + 255) / 256, 256>>>(ei, relidx);
    k_scan<<<1, 1024>>>();
    k_eamean1<<<64, 128>>>(relations);
    k_eamean2<<<1, 128>>>();
    k_copyrel<<<(NR * NF + 255) / 256, 256>>>(relations);
    k_scatter<<<(NE + 255) / 256, 256>>>(ei, relidx);
    k_selfloop<<<(NN + 255) / 256, 256>>>();

    dim3 grid_n(4, (NN + 127) / 128);
    dim3 grid_r(4, (NR + 1 + 127) / 128);

    const float* Hin = x;
    for (int l = 0; l < NL; l++) {
        const float* Wl_l = Wl + (size_t)l * NF * HC;
        const float* Wr_l = Wr + (size_t)l * NF * HC;
        const float* We_l = We + (size_t)l * NF * HC;
        gemm_tf32<<<grid_n, 256>>>(Hin, Wl_l, bl + (size_t)l * HC, pXL, NN);
        gemm_tf32<<<grid_n, 256>>>(Hin, Wr_l, br + (size_t)l * HC, pXR, NN);
        gemm_tf32<<<grid_r, 256>>>(pRelext, We_l, nullptr, pREL, NR + 1);

        float* Hout = pH + (size_t)(l & 1) * NN * NF;
        k_fused<<<NN, 128>>>(att + (size_t)l * NH * NF,
                             bias + (size_t)l * NF, Hout);
        Hin = Hout;
    }

    k_output<<<(NN * NF + 255) / 256, 256>>>(Hin, relations, (float*)d_out, out_size);
}

// round 5
// speedup vs baseline: 2.1937x; 1.2095x over previous
#include <cuda_runtime.h>
#include <cuda_bf16.h>
#include <math.h>

// Problem constants (fixed by the dataset)
#define NN   20000     // nodes
#define NE   100000    // edges (without self loops)
#define NR   1000      // relations
#define NF   128       // feature dim
#define NH   4         // heads
#define NL   4         // layers
#define HC   512       // NH*NF
#define ETOT (NE + NN) // edges incl self loops = 120000

// ---------------- scratch (static device globals; no runtime allocation) ----
__device__ float g_XL[(size_t)NN * HC];        // 41 MB  source projection
__device__ float g_XR[(size_t)NN * HC];        // 41 MB  target projection
__device__ float g_REL[(size_t)(NR + 1) * HC]; // 2 MB   edge embeddings (row NR = mean)
__device__ float g_relext[(size_t)(NR + 1) * NF]; // relations + mean row
__device__ float g_H[2 * (size_t)NN * NF];     // ping-pong node features
__device__ float g_part[125][NF];              // eamean partials
__device__ int   g_cnt[NN];
__device__ int   g_rcnt[NR];
__device__ int   g_rowptr[NN + 1];
__device__ int   g_offs[NN];
__device__ int   g_esrc[ETOT];
__device__ int   g_erel[ETOT];

// ---------------- preprocessing kernels -------------------------------------
__global__ void k_reset() {
    int i = blockIdx.x * blockDim.x + threadIdx.x;
    if (i < NN) g_cnt[i] = 1;              // self loop pre-counted
    if (i < NR) g_rcnt[i] = 0;
}

__global__ void k_hist(const int* __restrict__ ei, const int* __restrict__ relidx) {
    int e = blockIdx.x * blockDim.x + threadIdx.x;
    if (e < NE) {
        atomicAdd(&g_cnt[ei[NE + e]], 1);  // dst row
        atomicAdd(&g_rcnt[relidx[e]], 1);
    }
}

// single-block scan over 20000 counts -> rowptr + offs
__global__ void k_scan() {
    __shared__ int s[1024];
    int t = threadIdx.x;
    const int CH = 20;                      // 1024*20 >= 20000
    int beg = t * CH, end = min(beg + CH, NN);
    int sum = 0;
    for (int i = beg; i < end; i++) sum += g_cnt[i];
    s[t] = sum;
    __syncthreads();
    for (int off = 1; off < 1024; off <<= 1) {
        int v = (t >= off) ? s[t - off] : 0;
        __syncthreads();
        s[t] += v;
        __syncthreads();
    }
    int base = (t == 0) ? 0 : s[t - 1];
    for (int i = beg; i < end; i++) {
        g_rowptr[i] = base;
        g_offs[i]   = base;
        base += g_cnt[i];
    }
    if (t == 1023) g_rowptr[NN] = s[1023];
}

// eamean stage 1: 125 blocks x 128 threads, 8 relations each
__global__ void k_eamean1(const float* __restrict__ relations) {
    int b = blockIdx.x, f = threadIdx.x;
    float s = 0.0f;
#pragma unroll
    for (int j = 0; j < 8; j++) {
        int r = b * 8 + j;
        s += (float)g_rcnt[r] * __ldg(relations + (size_t)r * NF + f);
    }
    g_part[b][f] = s;
}

// eamean stage 2: combine 125 partials (deterministic)
__global__ void k_eamean2() {
    int f = threadIdx.x;
    float s = 0.0f;
#pragma unroll 5
    for (int b = 0; b < 125; b++) s += g_part[b][f];
    g_relext[(size_t)NR * NF + f] = s * (1.0f / NE);
}

// copy relations into relext AND into the output's second region
__global__ void k_copyrel(const float* __restrict__ relations,
                          float* __restrict__ out, int out_size) {
    int i = blockIdx.x * blockDim.x + threadIdx.x;
    if (i < NR * NF) {
        float v = relations[i];
        g_relext[i] = v;
        if (out_size >= NN * NF + NR * NF) out[NN * NF + i] = v;
    }
}

__global__ void k_scatter(const int* __restrict__ ei, const int* __restrict__ relidx) {
    int e = blockIdx.x * blockDim.x + threadIdx.x;
    if (e >= NE) return;
    int s = ei[e], d = ei[NE + e];
    int pos = atomicAdd(&g_offs[d], 1);
    g_esrc[pos] = s;
    g_erel[pos] = relidx[e];
}

__global__ void k_selfloop() {
    int n = blockIdx.x * blockDim.x + threadIdx.x;
    if (n >= NN) return;
    int pos = atomicAdd(&g_offs[n], 1);
    g_esrc[pos] = n;
    g_erel[pos] = NR;                       // mean-attr row
}

// ---------------- tf32 tensor-core GEMM -------------------------------------
// One launch per layer: blockIdx.z selects {XL, XR, REL} problem.
__device__ __forceinline__ unsigned f2tf(float x) {
    unsigned r;
    asm("cvt.rna.tf32.f32 %0, %1;" : "=r"(r) : "f"(x));
    return r;
}

__device__ __forceinline__ void mma_tf32(float* c, const unsigned* a,
                                         unsigned b0, unsigned b1) {
    asm("mma.sync.aligned.m16n8k8.row.col.f32.tf32.tf32.f32 "
        "{%0,%1,%2,%3},{%4,%5,%6,%7},{%8,%9},{%0,%1,%2,%3};"
        : "+f"(c[0]), "+f"(c[1]), "+f"(c[2]), "+f"(c[3])
        : "r"(a[0]), "r"(a[1]), "r"(a[2]), "r"(a[3]), "r"(b0), "r"(b1));
}

#define AS_STRIDE 36
#define BS_STRIDE 136

__global__ void __launch_bounds__(256)
gemm3_tf32(const float* __restrict__ Hin,
           const float* __restrict__ Wl, const float* __restrict__ bl,
           const float* __restrict__ Wr, const float* __restrict__ br,
           const float* __restrict__ We,
           float* __restrict__ XL, float* __restrict__ XR, float* __restrict__ REL) {
    const float* A; const float* B; const float* bias; float* C; int M;
    int z = blockIdx.z;
    if (z == 0)      { A = Hin;      B = Wl; bias = bl;      C = XL;  M = NN; }
    else if (z == 1) { A = Hin;      B = Wr; bias = br;      C = XR;  M = NN; }
    else             { A = g_relext; B = We; bias = nullptr; C = REL; M = NR + 1;
                       if (blockIdx.y * 128 >= NR + 1) return; }

    __shared__ float As[128 * AS_STRIDE];
    __shared__ float Bs[32 * BS_STRIDE];
    int t = threadIdx.x;
    int warp = t >> 5, lane = t & 31;
    int g = lane >> 2, tg = lane & 3;
    int m0 = blockIdx.y * 128, n0 = blockIdx.x * 128;
    int wm = (warp >> 1) * 32;
    int wn = (warp & 1) * 64;

    float acc[2][8][4] = {};

    for (int kc = 0; kc < 4; kc++) {
#pragma unroll
        for (int i = 0; i < 4; i++) {
            int flat = i * 256 + t;
            int row = flat >> 3, c4 = flat & 7;
            float4 v = make_float4(0.f, 0.f, 0.f, 0.f);
            int gr = m0 + row;
            if (gr < M) v = __ldg((const float4*)(A + (size_t)gr * NF + kc * 32) + c4);
            *(float4*)&As[row * AS_STRIDE + c4 * 4] = v;
        }
#pragma unroll
        for (int i = 0; i < 4; i++) {
            int flat = i * 256 + t;
            int kr = flat >> 5, c4 = flat & 31;
            float4 v = __ldg((const float4*)(B + (size_t)(kc * 32 + kr) * HC + n0) + c4);
            *(float4*)&Bs[kr * BS_STRIDE + c4 * 4] = v;
        }
        __syncthreads();

#pragma unroll
        for (int ks = 0; ks < 4; ks++) {
            int k0 = ks * 8;
            unsigned a[2][4];
#pragma unroll
            for (int mf = 0; mf < 2; mf++) {
                int r = wm + mf * 16 + g;
                a[mf][0] = f2tf(As[r * AS_STRIDE + k0 + tg]);
                a[mf][1] = f2tf(As[(r + 8) * AS_STRIDE + k0 + tg]);
                a[mf][2] = f2tf(As[r * AS_STRIDE + k0 + tg + 4]);
                a[mf][3] = f2tf(As[(r + 8) * AS_STRIDE + k0 + tg + 4]);
            }
#pragma unroll
            for (int nf = 0; nf < 8; nf++) {
                int c = wn + nf * 8 + g;
                unsigned b0 = f2tf(Bs[(k0 + tg) * BS_STRIDE + c]);
                unsigned b1 = f2tf(Bs[(k0 + tg + 4) * BS_STRIDE + c]);
                mma_tf32(acc[0][nf], a[0], b0, b1);
                mma_tf32(acc[1][nf], a[1], b0, b1);
            }
        }
        __syncthreads();
    }

#pragma unroll
    for (int nf = 0; nf < 8; nf++) {
        int col = n0 + wn + nf * 8 + 2 * tg;
        float2 bi = make_float2(0.f, 0.f);
        if (bias) bi = *(const float2*)(bias + col);
#pragma unroll
        for (int mf = 0; mf < 2; mf++) {
            int row = m0 + wm + mf * 16 + g;
            if (row < M) {
                float2 o = make_float2(acc[mf][nf][0] + bi.x, acc[mf][nf][1] + bi.y);
                *(float2*)(C + (size_t)row * HC + col) = o;
            }
            if (row + 8 < M) {
                float2 o = make_float2(acc[mf][nf][2] + bi.x, acc[mf][nf][3] + bi.y);
                *(float2*)(C + (size_t)(row + 8) * HC + col) = o;
            }
        }
    }
}

// ---------------- fused score + softmax + aggregate --------------------------
// One block (128 threads = 4 warps) per dst node; warp h owns head h.
// Online softmax, 2-way unrolled edge loop to interleave SHFL chains.
__global__ void __launch_bounds__(128)
k_fused(const float* __restrict__ att_l, const float* __restrict__ bias_l,
        float* __restrict__ Hout) {
    int n = blockIdx.x;
    int t = threadIdx.x;
    int h = t >> 5, lane = t & 31;
    int b0 = g_rowptr[n], b1 = g_rowptr[n + 1];

    int o = h * 32 + lane;                    // float4 index into a 512-f row
    const float4* XL4 = (const float4*)g_XL;
    const float4* RR4 = (const float4*)g_REL;
    float4 xr = __ldg((const float4*)g_XR + (size_t)n * 128 + o);
    float4 aw = __ldg((const float4*)att_l + o);

    float m = -1e30f, den = 0.0f;
    float4 acc = make_float4(0.f, 0.f, 0.f, 0.f);

    int i = b0;
    for (; i + 2 <= b1; i += 2) {
        int s0 = g_esrc[i],     r0 = g_erel[i];
        int s1 = g_esrc[i + 1], r1 = g_erel[i + 1];
        float4 xl0 = __ldg(XL4 + (size_t)s0 * 128 + o);
        float4 rr0 = __ldg(RR4 + (size_t)r0 * 128 + o);
        float4 xl1 = __ldg(XL4 + (size_t)s1 * 128 + o);
        float4 rr1 = __ldg(RR4 + (size_t)r1 * 128 + o);

        float ax = xl0.x + xr.x + rr0.x; ax = ax > 0.f ? ax : 0.2f * ax;
        float ay = xl0.y + xr.y + rr0.y; ay = ay > 0.f ? ay : 0.2f * ay;
        float az = xl0.z + xr.z + rr0.z; az = az > 0.f ? az : 0.2f * az;
        float aw_ = xl0.w + xr.w + rr0.w; aw_ = aw_ > 0.f ? aw_ : 0.2f * aw_;
        float l0 = ax * aw.x + ay * aw.y + az * aw.z + aw_ * aw.w;

        float bx = xl1.x + xr.x + rr1.x; bx = bx > 0.f ? bx : 0.2f * bx;
        float by = xl1.y + xr.y + rr1.y; by = by > 0.f ? by : 0.2f * by;
        float bz = xl1.z + xr.z + rr1.z; bz = bz > 0.f ? bz : 0.2f * bz;
        float bw = xl1.w + xr.w + rr1.w; bw = bw > 0.f ? bw : 0.2f * bw;
        float l1 = bx * aw.x + by * aw.y + bz * aw.z + bw * aw.w;

#pragma unroll
        for (int off = 16; off; off >>= 1) {
            l0 += __shfl_xor_sync(0xFFFFFFFFu, l0, off);
            l1 += __shfl_xor_sync(0xFFFFFFFFu, l1, off);
        }

        float mn = fmaxf(m, fmaxf(l0, l1));
        float sc = __expf(m - mn);            // m=-1e30 first iter -> sc=0
        den *= sc;
        acc.x *= sc; acc.y *= sc; acc.z *= sc; acc.w *= sc;
        m = mn;
        float w0 = __expf(l0 - m);
        float w1 = __expf(l1 - m);
        den += w0 + w1;
        acc.x += w0 * xl0.x + w1 * xl1.x;
        acc.y += w0 * xl0.y + w1 * xl1.y;
        acc.z += w0 * xl0.z + w1 * xl1.z;
        acc.w += w0 * xl0.w + w1 * xl1.w;
    }
    if (i < b1) {
        int s0 = g_esrc[i], r0 = g_erel[i];
        float4 xl0 = __ldg(XL4 + (size_t)s0 * 128 + o);
        float4 rr0 = __ldg(RR4 + (size_t)r0 * 128 + o);
        float ax = xl0.x + xr.x + rr0.x; ax = ax > 0.f ? ax : 0.2f * ax;
        float ay = xl0.y + xr.y + rr0.y; ay = ay > 0.f ? ay : 0.2f * ay;
        float az = xl0.z + xr.z + rr0.z; az = az > 0.f ? az : 0.2f * az;
        float aw_ = xl0.w + xr.w + rr0.w; aw_ = aw_ > 0.f ? aw_ : 0.2f * aw_;
        float l0 = ax * aw.x + ay * aw.y + az * aw.z + aw_ * aw.w;
#pragma unroll
        for (int off = 16; off; off >>= 1)
            l0 += __shfl_xor_sync(0xFFFFFFFFu, l0, off);
        float mn = fmaxf(m, l0);
        float sc = __expf(m - mn);
        den *= sc;
        acc.x *= sc; acc.y *= sc; acc.z *= sc; acc.w *= sc;
        m = mn;
        float w0 = __expf(l0 - m);
        den += w0;
        acc.x += w0 * xl0.x; acc.y += w0 * xl0.y;
        acc.z += w0 * xl0.z; acc.w += w0 * xl0.w;
    }

    // head mean (0.25/den) + cross-head combine via smem
    __shared__ float sacc[NH][NF];
    float sc = 0.25f / den;
    sacc[h][lane * 4 + 0] = acc.x * sc;
    sacc[h][lane * 4 + 1] = acc.y * sc;
    sacc[h][lane * 4 + 2] = acc.z * sc;
    sacc[h][lane * 4 + 3] = acc.w * sc;
    __syncthreads();
    float out = sacc[0][t] + sacc[1][t] + sacc[2][t] + sacc[3][t]
              + __ldg(bias_l + t);
    Hout[(size_t)n * NF + t] = out;
}

// ---------------- launch ------------------------------------------------------
extern "C" void kernel_launch(void* const* d_in, const int* in_sizes, int n_in,
                              void* d_out, int out_size) {
    const float* x         = (const float*)d_in[0];
    const int*   ei        = (const int*)d_in[1];
    const float* relations = (const float*)d_in[2];
    const int*   relidx    = (const int*)d_in[3];
    const float* Wl        = (const float*)d_in[4];
    const float* bl        = (const float*)d_in[5];
    const float* Wr        = (const float*)d_in[6];
    const float* br        = (const float*)d_in[7];
    const float* We        = (const float*)d_in[8];
    const float* att       = (const float*)d_in[9];
    const float* bias      = (const float*)d_in[10];

    float *pXL, *pXR, *pREL, *pH;
    cudaGetSymbolAddress((void**)&pXL, g_XL);
    cudaGetSymbolAddress((void**)&pXR, g_XR);
    cudaGetSymbolAddress((void**)&pREL, g_REL);
    cudaGetSymbolAddress((void**)&pH, g_H);

    // ---- preprocessing (rebuilt every call: graph replay safe) ----
    k_reset<<<(NN + 255) / 256, 256>>>();
    k_hist<<<(NE + 255) / 256, 256>>>(ei, relidx);
    k_scan<<<1, 1024>>>();
    k_eamean1<<<125, 128>>>(relations);
    k_eamean2<<<1, 128>>>();
    k_copyrel<<<(NR * NF + 255) / 256, 256>>>(relations, (float*)d_out, out_size);
    k_scatter<<<(NE + 255) / 256, 256>>>(ei, relidx);
    k_selfloop<<<(NN + 255) / 256, 256>>>();

    dim3 grid3(4, (NN + 127) / 128, 3);     // z: XL, XR, REL

    const float* Hin = x;
    for (int l = 0; l < NL; l++) {
        gemm3_tf32<<<grid3, 256>>>(Hin,
                                   Wl + (size_t)l * NF * HC, bl + (size_t)l * HC,
                                   Wr + (size_t)l * NF * HC, br + (size_t)l * HC,
                                   We + (size_t)l * NF * HC,
                                   pXL, pXR, pREL);

        float* Hout = (l == NL - 1) ? (float*)d_out
                                    : pH + (size_t)(l & 1) * NN * NF;
        k_fused<<<NN, 128>>>(att + (size_t)l * NH * NF,
                             bias + (size_t)l * NF, Hout);
        Hin = Hout;
    }
}

// round 6
// speedup vs baseline: 2.1956x; 1.0008x over previous
#include <cuda_runtime.h>
#include <cuda_bf16.h>
#include <math.h>

// Problem constants (fixed by the dataset)
#define NN   20000     // nodes
#define NE   100000    // edges (without self loops)
#define NR   1000      // relations
#define NF   128       // feature dim
#define NH   4         // heads
#define NL   4         // layers
#define HC   512       // NH*NF
#define ETOT (NE + NN) // edges incl self loops = 120000

// ---------------- scratch (static device globals; no runtime allocation) ----
__device__ float g_XL[(size_t)NN * HC];        // 41 MB  source projection
__device__ float g_XR[(size_t)NN * HC];        // 41 MB  target projection
__device__ float g_REL[(size_t)(NR + 1) * HC]; // 2 MB   edge embeddings (row NR = mean)
__device__ float g_relext[(size_t)(NR + 1) * NF]; // relations + mean row
__device__ float g_H[2 * (size_t)NN * NF];     // ping-pong node features
__device__ float g_part[125][NF];              // eamean partials
__device__ int   g_cnt[NN];
__device__ int   g_rcnt[NR];
__device__ int   g_rowptr[NN + 1];
__device__ int   g_offs[NN];
__device__ int   g_esrc[ETOT];
__device__ int   g_erel[ETOT];

// ---------------- preprocessing kernels -------------------------------------
// merged: reset histograms + copy relations into relext and output region
__global__ void k_init(const float* __restrict__ relations,
                       float* __restrict__ out, int out_size) {
    int i = blockIdx.x * blockDim.x + threadIdx.x;
    if (i < NN) g_cnt[i] = 1;              // self loop pre-counted
    if (i < NR) g_rcnt[i] = 0;
    if (i < NR * NF) {
        float v = relations[i];
        g_relext[i] = v;
        if (out_size >= NN * NF + NR * NF) out[NN * NF + i] = v;
    }
}

__global__ void k_hist(const int* __restrict__ ei, const int* __restrict__ relidx) {
    int e = blockIdx.x * blockDim.x + threadIdx.x;
    if (e < NE) {
        atomicAdd(&g_cnt[ei[NE + e]], 1);  // dst row
        atomicAdd(&g_rcnt[relidx[e]], 1);
    }
}

// single-block scan over 20000 counts -> rowptr + offs
__global__ void k_scan() {
    __shared__ int s[1024];
    int t = threadIdx.x;
    const int CH = 20;                      // 1024*20 >= 20000
    int beg = t * CH, end = min(beg + CH, NN);
    int sum = 0;
    for (int i = beg; i < end; i++) sum += g_cnt[i];
    s[t] = sum;
    __syncthreads();
    for (int off = 1; off < 1024; off <<= 1) {
        int v = (t >= off) ? s[t - off] : 0;
        __syncthreads();
        s[t] += v;
        __syncthreads();
    }
    int base = (t == 0) ? 0 : s[t - 1];
    for (int i = beg; i < end; i++) {
        g_rowptr[i] = base;
        g_offs[i]   = base;
        base += g_cnt[i];
    }
    if (t == 1023) g_rowptr[NN] = s[1023];
}

// eamean stage 1: 125 blocks x 128 threads, 8 relations each
__global__ void k_eamean1(const float* __restrict__ relations) {
    int b = blockIdx.x, f = threadIdx.x;
    float s = 0.0f;
#pragma unroll
    for (int j = 0; j < 8; j++) {
        int r = b * 8 + j;
        s += (float)g_rcnt[r] * __ldg(relations + (size_t)r * NF + f);
    }
    g_part[b][f] = s;
}

// eamean stage 2: combine 125 partials (deterministic)
__global__ void k_eamean2() {
    int f = threadIdx.x;
    float s = 0.0f;
#pragma unroll 5
    for (int b = 0; b < 125; b++) s += g_part[b][f];
    g_relext[(size_t)NR * NF + f] = s * (1.0f / NE);
}

// merged: scatter edges + self loops (counting-sort by dst)
__global__ void k_scatter(const int* __restrict__ ei, const int* __restrict__ relidx) {
    int e = blockIdx.x * blockDim.x + threadIdx.x;
    if (e < NE) {
        int s = ei[e], d = ei[NE + e];
        int pos = atomicAdd(&g_offs[d], 1);
        g_esrc[pos] = s;
        g_erel[pos] = relidx[e];
    } else if (e < NE + NN) {
        int n = e - NE;
        int pos = atomicAdd(&g_offs[n], 1);
        g_esrc[pos] = n;
        g_erel[pos] = NR;                   // mean-attr row
    }
}

// ---------------- tf32 tensor-core GEMM -------------------------------------
// One launch per layer: blockIdx.z selects {XL, XR, REL} problem.
// tf32 conversion done once at SMEM-store; double-buffered K-chunk pipeline.
__device__ __forceinline__ unsigned f2tf(float x) {
    unsigned r;
    asm("cvt.rna.tf32.f32 %0, %1;" : "=r"(r) : "f"(x));
    return r;
}

__device__ __forceinline__ void mma_tf32(float* c, const unsigned* a,
                                         unsigned b0, unsigned b1) {
    asm("mma.sync.aligned.m16n8k8.row.col.f32.tf32.tf32.f32 "
        "{%0,%1,%2,%3},{%4,%5,%6,%7},{%8,%9},{%0,%1,%2,%3};"
        : "+f"(c[0]), "+f"(c[1]), "+f"(c[2]), "+f"(c[3])
        : "r"(a[0]), "r"(a[1]), "r"(a[2]), "r"(a[3]), "r"(b0), "r"(b1));
}

#define AS_STRIDE 36                 // banks (4g+tg) distinct mod 32
#define BS_STRIDE 136                // banks (8tg+g) distinct mod 32
#define ASZ (128 * AS_STRIDE)        // u32 per A buffer
#define BSZ (32 * BS_STRIDE)         // u32 per B buffer
#define GEMM_SMEM_BYTES (2 * (ASZ + BSZ) * 4)   // 71680

__global__ void __launch_bounds__(256)
gemm3_tf32(const float* __restrict__ Hin,
           const float* __restrict__ Wl, const float* __restrict__ bl,
           const float* __restrict__ Wr, const float* __restrict__ br,
           const float* __restrict__ We,
           float* __restrict__ XL, float* __restrict__ XR, float* __restrict__ REL) {
    const float* A; const float* B; const float* bias; float* C; int M;
    int z = blockIdx.z;
    if (z == 0)      { A = Hin;      B = Wl; bias = bl;      C = XL;  M = NN; }
    else if (z == 1) { A = Hin;      B = Wr; bias = br;      C = XR;  M = NN; }
    else             { A = g_relext; B = We; bias = nullptr; C = REL; M = NR + 1;
                       if (blockIdx.y * 128 >= NR + 1) return; }

    extern __shared__ unsigned smem[];
    unsigned* Abuf[2] = { smem, smem + ASZ };
    unsigned* Bbuf[2] = { smem + 2 * ASZ, smem + 2 * ASZ + BSZ };

    int t = threadIdx.x;
    int warp = t >> 5, lane = t & 31;
    int g = lane >> 2, tg = lane & 3;
    int m0 = blockIdx.y * 128, n0 = blockIdx.x * 128;
    int wm = (warp >> 1) * 32;
    int wn = (warp & 1) * 64;

    // per-thread load/store coordinates
    int arow = t >> 1, ac4 = t & 1;          // A: 128 rows x 8 float4 -> 2 f4/thread? no:
    // A chunk is 128x32 floats = 1024 float4; 256 threads -> 4 each.
    // B chunk is 32x128 floats = 1024 float4; 4 each.
    float4 ar[4], br4[4];

    auto ldA = [&](int kc) {
#pragma unroll
        for (int i = 0; i < 4; i++) {
            int flat = i * 256 + t;
            int row = flat >> 3, c4 = flat & 7;
            int gr = m0 + row;
            ar[i] = (gr < M)
                ? __ldg((const float4*)(A + (size_t)gr * NF + kc * 32) + c4)
                : make_float4(0.f, 0.f, 0.f, 0.f);
        }
    };
    auto ldB = [&](int kc) {
#pragma unroll
        for (int i = 0; i < 4; i++) {
            int flat = i * 256 + t;
            int kr = flat >> 5, c4 = flat & 31;
            br4[i] = __ldg((const float4*)(B + (size_t)(kc * 32 + kr) * HC + n0) + c4);
        }
    };
    auto stAB = [&](int buf) {
        unsigned* As = Abuf[buf];
        unsigned* Bs = Bbuf[buf];
#pragma unroll
        for (int i = 0; i < 4; i++) {
            int flat = i * 256 + t;
            int row = flat >> 3, c4 = flat & 7;
            uint4 v = make_uint4(f2tf(ar[i].x), f2tf(ar[i].y),
                                 f2tf(ar[i].z), f2tf(ar[i].w));
            *(uint4*)&As[row * AS_STRIDE + c4 * 4] = v;
        }
#pragma unroll
        for (int i = 0; i < 4; i++) {
            int flat = i * 256 + t;
            int kr = flat >> 5, c4 = flat & 31;
            uint4 v = make_uint4(f2tf(br4[i].x), f2tf(br4[i].y),
                                 f2tf(br4[i].z), f2tf(br4[i].w));
            *(uint4*)&Bs[kr * BS_STRIDE + c4 * 4] = v;
        }
    };

    float acc[2][8][4] = {};

    ldA(0); ldB(0);
    stAB(0);
    __syncthreads();

    for (int kc = 0; kc < 4; kc++) {
        if (kc < 3) { ldA(kc + 1); ldB(kc + 1); }   // prefetch (LDGs in flight)

        const unsigned* As = Abuf[kc & 1];
        const unsigned* Bs = Bbuf[kc & 1];
#pragma unroll
        for (int ks = 0; ks < 4; ks++) {
            int k0 = ks * 8;
            unsigned a[2][4];
#pragma unroll
            for (int mf = 0; mf < 2; mf++) {
                int r = wm + mf * 16 + g;
                a[mf][0] = As[r * AS_STRIDE + k0 + tg];
                a[mf][1] = As[(r + 8) * AS_STRIDE + k0 + tg];
                a[mf][2] = As[r * AS_STRIDE + k0 + tg + 4];
                a[mf][3] = As[(r + 8) * AS_STRIDE + k0 + tg + 4];
            }
#pragma unroll
            for (int nf = 0; nf < 8; nf++) {
                int c = wn + nf * 8 + g;
                unsigned b0 = Bs[(k0 + tg) * BS_STRIDE + c];
                unsigned b1 = Bs[(k0 + tg + 4) * BS_STRIDE + c];
                mma_tf32(acc[0][nf], a[0], b0, b1);
                mma_tf32(acc[1][nf], a[1], b0, b1);
            }
        }
        if (kc < 3) {
            stAB((kc + 1) & 1);
            __syncthreads();
        }
    }

#pragma unroll
    for (int nf = 0; nf < 8; nf++) {
        int col = n0 + wn + nf * 8 + 2 * tg;
        float2 bi = make_float2(0.f, 0.f);
        if (bias) bi = *(const float2*)(bias + col);
#pragma unroll
        for (int mf = 0; mf < 2; mf++) {
            int row = m0 + wm + mf * 16 + g;
            if (row < M) {
                float2 o = make_float2(acc[mf][nf][0] + bi.x, acc[mf][nf][1] + bi.y);
                *(float2*)(C + (size_t)row * HC + col) = o;
            }
            if (row + 8 < M) {
                float2 o = make_float2(acc[mf][nf][2] + bi.x, acc[mf][nf][3] + bi.y);
                *(float2*)(C + (size_t)(row + 8) * HC + col) = o;
            }
        }
    }
}

// ---------------- fused score + softmax + aggregate --------------------------
// One block (128 threads = 4 warps) per dst node; warp h owns head h.
// Online softmax, 2-way unrolled edge loop to interleave SHFL chains.
__global__ void __launch_bounds__(128)
k_fused(const float* __restrict__ att_l, const float* __restrict__ bias_l,
        float* __restrict__ Hout) {
    int n = blockIdx.x;
    int t = threadIdx.x;
    int h = t >> 5, lane = t & 31;
    int b0 = g_rowptr[n], b1 = g_rowptr[n + 1];

    int o = h * 32 + lane;                    // float4 index into a 512-f row
    const float4* XL4 = (const float4*)g_XL;
    const float4* RR4 = (const float4*)g_REL;
    float4 xr = __ldg((const float4*)g_XR + (size_t)n * 128 + o);
    float4 aw = __ldg((const float4*)att_l + o);

    float m = -1e30f, den = 0.0f;
    float4 acc = make_float4(0.f, 0.f, 0.f, 0.f);

    int i = b0;
    for (; i + 2 <= b1; i += 2) {
        int s0 = g_esrc[i],     r0 = g_erel[i];
        int s1 = g_esrc[i + 1], r1 = g_erel[i + 1];
        float4 xl0 = __ldg(XL4 + (size_t)s0 * 128 + o);
        float4 rr0 = __ldg(RR4 + (size_t)r0 * 128 + o);
        float4 xl1 = __ldg(XL4 + (size_t)s1 * 128 + o);
        float4 rr1 = __ldg(RR4 + (size_t)r1 * 128 + o);

        float ax = xl0.x + xr.x + rr0.x; ax = ax > 0.f ? ax : 0.2f * ax;
        float ay = xl0.y + xr.y + rr0.y; ay = ay > 0.f ? ay : 0.2f * ay;
        float az = xl0.z + xr.z + rr0.z; az = az > 0.f ? az : 0.2f * az;
        float aw_ = xl0.w + xr.w + rr0.w; aw_ = aw_ > 0.f ? aw_ : 0.2f * aw_;
        float l0 = ax * aw.x + ay * aw.y + az * aw.z + aw_ * aw.w;

        float bx = xl1.x + xr.x + rr1.x; bx = bx > 0.f ? bx : 0.2f * bx;
        float by = xl1.y + xr.y + rr1.y; by = by > 0.f ? by : 0.2f * by;
        float bz = xl1.z + xr.z + rr1.z; bz = bz > 0.f ? bz : 0.2f * bz;
        float bw = xl1.w + xr.w + rr1.w; bw = bw > 0.f ? bw : 0.2f * bw;
        float l1 = bx * aw.x + by * aw.y + bz * aw.z + bw * aw.w;

#pragma unroll
        for (int off = 16; off; off >>= 1) {
            l0 += __shfl_xor_sync(0xFFFFFFFFu, l0, off);
            l1 += __shfl_xor_sync(0xFFFFFFFFu, l1, off);
        }

        float mn = fmaxf(m, fmaxf(l0, l1));
        float sc = __expf(m - mn);            // m=-1e30 first iter -> sc=0
        den *= sc;
        acc.x *= sc; acc.y *= sc; acc.z *= sc; acc.w *= sc;
        m = mn;
        float w0 = __expf(l0 - m);
        float w1 = __expf(l1 - m);
        den += w0 + w1;
        acc.x += w0 * xl0.x + w1 * xl1.x;
        acc.y += w0 * xl0.y + w1 * xl1.y;
        acc.z += w0 * xl0.z + w1 * xl1.z;
        acc.w += w0 * xl0.w + w1 * xl1.w;
    }
    if (i < b1) {
        int s0 = g_esrc[i], r0 = g_erel[i];
        float4 xl0 = __ldg(XL4 + (size_t)s0 * 128 + o);
        float4 rr0 = __ldg(RR4 + (size_t)r0 * 128 + o);
        float ax = xl0.x + xr.x + rr0.x; ax = ax > 0.f ? ax : 0.2f * ax;
        float ay = xl0.y + xr.y + rr0.y; ay = ay > 0.f ? ay : 0.2f * ay;
        float az = xl0.z + xr.z + rr0.z; az = az > 0.f ? az : 0.2f * az;
        float aw_ = xl0.w + xr.w + rr0.w; aw_ = aw_ > 0.f ? aw_ : 0.2f * aw_;
        float l0 = ax * aw.x + ay * aw.y + az * aw.z + aw_ * aw.w;
#pragma unroll
        for (int off = 16; off; off >>= 1)
            l0 += __shfl_xor_sync(0xFFFFFFFFu, l0, off);
        float mn = fmaxf(m, l0);
        float sc = __expf(m - mn);
        den *= sc;
        acc.x *= sc; acc.y *= sc; acc.z *= sc; acc.w *= sc;
        m = mn;
        float w0 = __expf(l0 - m);
        den += w0;
        acc.x += w0 * xl0.x; acc.y += w0 * xl0.y;
        acc.z += w0 * xl0.z; acc.w += w0 * xl0.w;
    }

    // head mean (0.25/den) + cross-head combine via smem
    __shared__ float sacc[NH][NF];
    float sc = 0.25f / den;
    sacc[h][lane * 4 + 0] = acc.x * sc;
    sacc[h][lane * 4 + 1] = acc.y * sc;
    sacc[h][lane * 4 + 2] = acc.z * sc;
    sacc[h][lane * 4 + 3] = acc.w * sc;
    __syncthreads();
    float out = sacc[0][t] + sacc[1][t] + sacc[2][t] + sacc[3][t]
              + __ldg(bias_l + t);
    Hout[(size_t)n * NF + t] = out;
}

// ---------------- launch ------------------------------------------------------
extern "C" void kernel_launch(void* const* d_in, const int* in_sizes, int n_in,
                              void* d_out, int out_size) {
    const float* x         = (const float*)d_in[0];
    const int*   ei        = (const int*)d_in[1];
    const float* relations = (const float*)d_in[2];
    const int*   relidx    = (const int*)d_in[3];
    const float* Wl        = (const float*)d_in[4];
    const float* bl        = (const float*)d_in[5];
    const float* Wr        = (const float*)d_in[6];
    const float* br        = (const float*)d_in[7];
    const float* We        = (const float*)d_in[8];
    const float* att       = (const float*)d_in[9];
    const float* bias      = (const float*)d_in[10];

    float *pXL, *pXR, *pREL, *pH;
    cudaGetSymbolAddress((void**)&pXL, g_XL);
    cudaGetSymbolAddress((void**)&pXR, g_XR);
    cudaGetSymbolAddress((void**)&pREL, g_REL);
    cudaGetSymbolAddress((void**)&pH, g_H);

    cudaFuncSetAttribute(gemm3_tf32,
                         cudaFuncAttributeMaxDynamicSharedMemorySize,
                         GEMM_SMEM_BYTES);

    // ---- preprocessing (rebuilt every call: graph replay safe) ----
    k_init<<<(NR * NF + 255) / 256, 256>>>(relations, (float*)d_out, out_size);
    k_hist<<<(NE + 255) / 256, 256>>>(ei, relidx);
    k_scan<<<1, 1024>>>();
    k_eamean1<<<125, 128>>>(relations);
    k_eamean2<<<1, 128>>>();
    k_scatter<<<(NE + NN + 255) / 256, 256>>>(ei, relidx);

    dim3 grid3(4, (NN + 127) / 128, 3);     // z: XL, XR, REL

    const float* Hin = x;
    for (int l = 0; l < NL; l++) {
        gemm3_tf32<<<grid3, 256, GEMM_SMEM_BYTES>>>(
            Hin,
            Wl + (size_t)l * NF * HC, bl + (size_t)l * HC,
            Wr + (size_t)l * NF * HC, br + (size_t)l * HC,
            We + (size_t)l * NF * HC,
            pXL, pXR, pREL);

        float* Hout = (l == NL - 1) ? (float*)d_out
                                    : pH + (size_t)(l & 1) * NN * NF;
        k_fused<<<NN, 128>>>(att + (size_t)l * NH * NF,
                             bias + (size_t)l * NF, Hout);
        Hin = Hout;
    }
}